// round 9
// baseline (speedup 1.0000x reference)
#include <cuda_runtime.h>
#include <cuda_pipeline.h>

// DiceLoss: logits f32 [8,11,512,512], targets int32 [8,512,512] -> scalar f32.
// Persistent single-wave grid (148 SMs x 4 blocks) + cp.async 3-stage pipeline,
// one barrier per tile. Separate tiny finalize kernel (fusion regressed twice).
// loss = 1 - mean_c (2*I[c]+1)/(Card[c]+1)

#define NC     11
#define HW     (512 * 512)           // 2^18
#define NB     8
#define NPIX   (NB * HW)             // 2,097,152
#define IGN    255
#define NTHR   256
#define NWARP  (NTHR / 32)
#define TILE   256                   // pixels per tile (1 px/thread)
#define NTILES (NPIX / TILE)         // 8192
#define TPI    (HW / TILE)           // 1024 tiles per image
#define NBLK   592                   // 148 SMs * 4 blocks: exactly one wave
#define STAGES 3
#define LCH    (TILE / 4)            // 64 16B-chunks per channel row
#define CPT    3                     // (11*64 + 64)/256 chunks per thread

// Per-block partials: row c = intersection[c], row NC+c = cardinality[c].
__device__ float g_part[2 * NC][NBLK];

struct Tile {
    float logit[NC][TILE];   // 11 KB
    int   tgt[TILE];         // 1 KB
};

__global__ __launch_bounds__(NTHR, 4) void dice_main_kernel(
    const float* __restrict__ logits,
    const int*   __restrict__ targets)
{
    __shared__ Tile s_tile[STAGES];                    // 36 KB

    const int tid  = threadIdx.x;
    const int nloc = (NTILES - blockIdx.x + NBLK - 1) / NBLK;   // 13 or 14

    // Issue cp.async for global tile T into stage s; empty commit if T OOB.
    auto issue = [&](int li, int s) {
        const int T = blockIdx.x + li * NBLK;
        if (li < nloc) {
            const int b    = T >> 10;                  // T / TPI
            const int poff = (T & (TPI - 1)) * TILE;
            const float* lb = logits  + (size_t)b * (NC * HW) + poff;
            const int*   tb = targets + (size_t)b * HW + poff;
#pragma unroll
            for (int k = 0; k < CPT; k++) {
                const int idx = tid + k * NTHR;        // 0..767
                if (idx < NC * LCH) {                  // logits: 704 chunks
                    const int ch = idx >> 6;
                    const int w  = idx & (LCH - 1);
                    __pipeline_memcpy_async(&s_tile[s].logit[ch][w * 4],
                                            lb + (size_t)ch * HW + w * 4, 16);
                } else {                               // targets: 64 chunks
                    const int w = idx - NC * LCH;
                    __pipeline_memcpy_async(&s_tile[s].tgt[w * 4],
                                            tb + w * 4, 16);
                }
            }
        }
        __pipeline_commit();                           // uniform group cadence
    };

    float inter[NC];
    float card[NC];
#pragma unroll
    for (int c = 0; c < NC; c++) { inter[c] = 0.0f; card[c] = 0.0f; }

    // Prologue: prefetch local tiles 0 and 1.
    issue(0, 0);
    issue(1, 1);

    for (int i = 0; i < nloc; i++) {
        __pipeline_wait_prior(1);      // own copies of tile i complete
        __syncthreads();               // all copies visible; compute(i-1) done
        issue(i + 2, (i + 2) % STAGES);// overwrites stage read at i-1: safe

        const int s  = i % STAGES;
        const int tg = s_tile[s].tgt[tid];

        float e[NC];
        float denom = 0.0f;
#pragma unroll
        for (int c = 0; c < NC; c++) {
            e[c] = __expf(s_tile[s].logit[c][tid]);    // logits ~N(0,1): safe
            denom += e[c];
        }
        if (tg != IGN) {
            const float r = __frcp_rn(denom);
#pragma unroll
            for (int c = 0; c < NC; c++) {
                const float pr = e[c] * r;
                const bool  is = (tg == c);
                card[c]  += pr + (is ? 1.0f : 0.0f);
                inter[c] += is ? pr : 0.0f;
            }
        }
    }

    // Warp butterfly reduction
#pragma unroll
    for (int c = 0; c < NC; c++) {
#pragma unroll
        for (int o = 16; o > 0; o >>= 1) {
            inter[c] += __shfl_xor_sync(0xffffffffu, inter[c], o);
            card[c]  += __shfl_xor_sync(0xffffffffu, card[c], o);
        }
    }

    // Block reduction via shared; one plain store per class per block.
    __shared__ float s_inter[NWARP][NC];
    __shared__ float s_card [NWARP][NC];
    const int wid = tid >> 5;
    const int lid = tid & 31;
    if (lid == 0) {
#pragma unroll
        for (int c = 0; c < NC; c++) {
            s_inter[wid][c] = inter[c];
            s_card [wid][c] = card[c];
        }
    }
    __syncthreads();
    if (tid < NC) {
        float si = 0.0f, sc = 0.0f;
#pragma unroll
        for (int w = 0; w < NWARP; w++) {
            si += s_inter[w][tid];
            sc += s_card [w][tid];
        }
        g_part[tid][blockIdx.x]      = si;
        g_part[NC + tid][blockIdx.x] = sc;
    }
}

// One block, 22 warps: warp w reduces row w of g_part (592 entries).
__global__ __launch_bounds__(2 * NC * 32) void dice_finalize_kernel(
    float* __restrict__ out)
{
    __shared__ float s_row[2 * NC];
    const int w   = threadIdx.x >> 5;
    const int lid = threadIdx.x & 31;

    float s = 0.0f;
#pragma unroll
    for (int i = 0; i < (NBLK + 31) / 32; i++) {
        const int idx = lid + i * 32;
        if (idx < NBLK) s += g_part[w][idx];
    }
#pragma unroll
    for (int o = 16; o > 0; o >>= 1)
        s += __shfl_xor_sync(0xffffffffu, s, o);
    if (lid == 0) s_row[w] = s;
    __syncthreads();

    if (threadIdx.x == 0) {
        float acc = 0.0f;
#pragma unroll
        for (int c = 0; c < NC; c++)
            acc += (2.0f * s_row[c] + 1.0f) / (s_row[NC + c] + 1.0f);
        out[0] = 1.0f - acc / (float)NC;
    }
}

extern "C" void kernel_launch(void* const* d_in, const int* in_sizes, int n_in,
                              void* d_out, int out_size) {
    const float* logits  = (const float*)d_in[0];
    const int*   targets = (const int*)d_in[1];
    float*       out     = (float*)d_out;

    dice_main_kernel<<<NBLK, NTHR>>>(logits, targets);
    dice_finalize_kernel<<<1, 2 * NC * 32>>>(out);
}

// round 10
// speedup vs baseline: 1.0832x; 1.0832x over previous
#include <cuda_runtime.h>
#include <cuda_pipeline.h>

// DiceLoss: logits f32 [8,11,512,512], targets int32 [8,512,512] -> scalar f32.
// R8 cp.async pipeline structure + thinned per-pixel compute:
//   - class loop = 11 FFMAs only (sum of probs)
//   - intersection via 1 dynamic LDS + per-thread smem scatter column
//   - class-count histogram packed 5 bits/class in a u64 register
// loss = 1 - mean_c (2*I[c]+1)/(Card[c]+1)

#define NC     11
#define HW     (512 * 512)           // 2^18
#define NB     8
#define NPIX   (NB * HW)             // 2,097,152
#define IGN    255
#define NBLK   1024
#define NTHR   256
#define NWARP  (NTHR / 32)
#define PXBLK  (NPIX / NBLK)         // 2048 contiguous pixels per block
#define BPI    (HW / PXBLK)          // 128 blocks per image
#define TILE   256                   // 1 px/thread/tile
#define NT     (PXBLK / TILE)        // 8 tiles
#define STAGES 3
#define LCH    (TILE / 4)            // 64 16B-chunks per channel row
#define CPT    3                     // 768 chunks / 256 threads

// Per-block partials: row c = intersection[c], row NC+c = cardinality[c].
__device__ float g_part[2 * NC][NBLK];

struct Tile {
    float logit[NC][TILE];   // 11 KB
    int   tgt[TILE];         // 1 KB
};

__global__ __launch_bounds__(NTHR, 4) void dice_main_kernel(
    const float* __restrict__ logits,
    const int*   __restrict__ targets)
{
    // Tiles live during the pixel loop; reduction arrays overlay them after.
    __shared__ __align__(16) unsigned char s_raw[STAGES * sizeof(Tile)]; // 36 KB
    __shared__ float s_scat[NC][NTHR];                                   // 11 KB
    Tile* s_tile = (Tile*)s_raw;

    const int tid = threadIdx.x;
    const int b   = blockIdx.x >> 7;                   // / BPI
    const int p0  = (blockIdx.x & (BPI - 1)) * PXBLK;
    const float* lbase = logits  + (size_t)b * (NC * HW) + p0;
    const int*   tbase = targets + (size_t)b * HW + p0;

    auto issue = [&](int t, int s) {
        const int poff = t * TILE;
#pragma unroll
        for (int k = 0; k < CPT; k++) {
            const int idx = tid + k * NTHR;            // 0..767
            if (idx < NC * LCH) {                      // logits: 704 chunks
                const int ch = idx >> 6;
                const int w  = idx & (LCH - 1);
                __pipeline_memcpy_async(&s_tile[s].logit[ch][w * 4],
                                        lbase + (size_t)ch * HW + poff + w * 4, 16);
            } else {                                   // targets: 64 chunks
                const int w = idx - NC * LCH;
                __pipeline_memcpy_async(&s_tile[s].tgt[w * 4],
                                        tbase + poff + w * 4, 16);
            }
        }
        __pipeline_commit();
    };

    float sumP[NC];
#pragma unroll
    for (int c = 0; c < NC; c++) sumP[c] = 0.0f;
#pragma unroll
    for (int c = 0; c < NC; c++) s_scat[c][tid] = 0.0f;   // own column
    unsigned long long cnt = 0ull;                         // 5 bits/class, max 8

    issue(0, 0);
    issue(1, 1);

#pragma unroll
    for (int t = 0; t < NT; t++) {
        if (t >= 1) __syncthreads();       // stage (t+2)%3 free before overwrite
        if (t + 2 < NT) issue(t + 2, (t + 2) % STAGES);
        __pipeline_wait_prior((NT - 1 - t) >= 2 ? 2 : (NT - 1 - t));
        __syncthreads();                   // tile t visible to all threads

        const int s  = t % STAGES;
        const int tg = s_tile[s].tgt[tid];

        float e[NC];
        float denom = 0.0f;
#pragma unroll
        for (int c = 0; c < NC; c++) {
            e[c] = __expf(s_tile[s].logit[c][tid]);    // logits ~N(0,1): safe
            denom += e[c];
        }

        if (tg != IGN) {
            const float r = __frcp_rn(denom);
#pragma unroll
            for (int c = 0; c < NC; c++)               // 11 FFMAs, nothing else
                sumP[c] = fmaf(e[c], r, sumP[c]);
            // intersection: dynamic conflict-free LDS (bank = tid%32)
            const float pt = __expf(s_tile[s].logit[tg][tid]) * r;
            s_scat[tg][tid] += pt;                     // private column
            cnt += 1ull << (5 * tg);                   // packed histogram
        }
    }

    // Merge per-thread pieces
    float inter[NC];
    float card[NC];
#pragma unroll
    for (int c = 0; c < NC; c++) {
        inter[c] = s_scat[c][tid];
        card[c]  = sumP[c] + (float)((unsigned)(cnt >> (5 * c)) & 31u);
    }

    // Warp butterfly reduction
#pragma unroll
    for (int c = 0; c < NC; c++) {
#pragma unroll
        for (int o = 16; o > 0; o >>= 1) {
            inter[c] += __shfl_xor_sync(0xffffffffu, inter[c], o);
            card[c]  += __shfl_xor_sync(0xffffffffu, card[c], o);
        }
    }

    // Block reduction: overlay tile smem (dead now) with reduce arrays.
    __syncthreads();                       // all warps done reading tiles
    float (*s_ri)[NC] = (float(*)[NC])s_raw;          // [NWARP][NC]
    float (*s_rc)[NC] = ((float(*)[NC])s_raw) + NWARP;
    const int wid = tid >> 5;
    const int lid = tid & 31;
    if (lid == 0) {
#pragma unroll
        for (int c = 0; c < NC; c++) {
            s_ri[wid][c] = inter[c];
            s_rc[wid][c] = card[c];
        }
    }
    __syncthreads();
    if (tid < NC) {
        float si = 0.0f, sc = 0.0f;
#pragma unroll
        for (int w = 0; w < NWARP; w++) {
            si += s_ri[w][tid];
            sc += s_rc[w][tid];
        }
        g_part[tid][blockIdx.x]      = si;
        g_part[NC + tid][blockIdx.x] = sc;
    }
}

// One block, 22 warps: warp w reduces row w of g_part (1024 entries).
__global__ __launch_bounds__(2 * NC * 32) void dice_finalize_kernel(
    float* __restrict__ out)
{
    __shared__ float s_row[2 * NC];
    const int w   = threadIdx.x >> 5;
    const int lid = threadIdx.x & 31;

    float s = 0.0f;
#pragma unroll
    for (int i = 0; i < NBLK / 32; i++)
        s += g_part[w][lid + i * 32];
#pragma unroll
    for (int o = 16; o > 0; o >>= 1)
        s += __shfl_xor_sync(0xffffffffu, s, o);
    if (lid == 0) s_row[w] = s;
    __syncthreads();

    if (threadIdx.x == 0) {
        float acc = 0.0f;
#pragma unroll
        for (int c = 0; c < NC; c++)
            acc += (2.0f * s_row[c] + 1.0f) / (s_row[NC + c] + 1.0f);
        out[0] = 1.0f - acc / (float)NC;
    }
}

extern "C" void kernel_launch(void* const* d_in, const int* in_sizes, int n_in,
                              void* d_out, int out_size) {
    const float* logits  = (const float*)d_in[0];
    const int*   targets = (const int*)d_in[1];
    float*       out     = (float*)d_out;

    dice_main_kernel<<<NBLK, NTHR>>>(logits, targets);
    dice_finalize_kernel<<<1, 2 * NC * 32>>>(out);
}